// round 9
// baseline (speedup 1.0000x reference)
#include <cuda_runtime.h>
#include <cuda_bf16.h>
#include <math.h>

// Problem constants
#define BB   32
#define INF  128
#define HH   1024
#define OUTF 128
#define KCAT (INF + HH)   // 1152
#define TPB  256
#define RPB  8            // rows (warps) per block
#define HB   16           // batches per chain (BB/2)

// Scratch (allocation-free rule: __device__ globals)
__device__ float g_c0[BB * HH];
__device__ float g_c1[BB * HH];
__device__ float g_c2[BB * HH];

// ---------------------------------------------------------------------------
// R2/R7-proven matvec tile kernel: 8 warps/block = 8 consecutive rows of ONE
// batch; activation staged in smem once; W front-batched with __ldcs; tanh.
// ---------------------------------------------------------------------------
template <int K, bool LAYER0>
__global__ __launch_bounds__(TPB) void matvec_kernel(
    const float* __restrict__ W, const float* __restrict__ bias,
    const float* __restrict__ in0,   // LAYER0: x ; else: activations [B,K]
    const float* __restrict__ in1,   // LAYER0: hidden ; else unused
    float* __restrict__ out, int Hout, int row_off)
{
    __shared__ float4 xs[K / 4];

    const int rowbase = row_off + blockIdx.x * RPB;
    const int b = rowbase / Hout;

    if (LAYER0) {
        const float4* xv = reinterpret_cast<const float4*>(in0 + (size_t)b * INF);
        const float4* hv = reinterpret_cast<const float4*>(in1 + (size_t)b * HH);
#pragma unroll
        for (int i = threadIdx.x; i < K / 4; i += TPB)
            xs[i] = (i < INF / 4) ? xv[i] : hv[i - INF / 4];
    } else {
        const float4* src = reinterpret_cast<const float4*>(in0 + (size_t)b * K);
#pragma unroll
        for (int i = threadIdx.x; i < K / 4; i += TPB)
            xs[i] = src[i];
    }
    __syncthreads();

    const int warp = threadIdx.x >> 5;
    const int lane = threadIdx.x & 31;
    const int row  = rowbase + warp;
    const int o    = row - b * Hout;

    const float4* __restrict__ Wr = reinterpret_cast<const float4*>(W + (size_t)row * K);
    constexpr int NIT = K / 128;

    float4 w[NIT];
#pragma unroll
    for (int j = 0; j < NIT; j++)
        w[j] = __ldcs(Wr + j * 32 + lane);

    float sum = 0.f;
#pragma unroll
    for (int j = 0; j < NIT; j++) {
        float4 v = xs[j * 32 + lane];
        sum += w[j].x * v.x + w[j].y * v.y + w[j].z * v.z + w[j].w * v.w;
    }
#pragma unroll
    for (int off = 16; off; off >>= 1)
        sum += __shfl_xor_sync(0xFFFFFFFFu, sum, off);

    if (lane == 0)
        out[row] = tanhf(sum + bias[o]);
}

// ---------------------------------------------------------------------------
// Fused Wo + log_softmax: one block per batch. 8 warps compute the 128-row
// matvec (16 rows/warp), logits to smem, warp 0 does log_softmax -> out.
// ---------------------------------------------------------------------------
__global__ __launch_bounds__(TPB) void wo_softmax_kernel(
    const float* __restrict__ Wo, const float* __restrict__ bo,
    float* __restrict__ out, int boff)
{
    __shared__ float4 xs[HH / 4];
    __shared__ float logits[OUTF];

    const int b = boff + blockIdx.x;
    {
        const float4* src = reinterpret_cast<const float4*>(g_c2 + (size_t)b * HH);
#pragma unroll
        for (int i = threadIdx.x; i < HH / 4; i += TPB)
            xs[i] = src[i];
    }
    __syncthreads();

    const int warp = threadIdx.x >> 5;
    const int lane = threadIdx.x & 31;

    for (int r = warp; r < OUTF; r += 8) {
        const float4* __restrict__ Wr =
            reinterpret_cast<const float4*>(Wo + ((size_t)b * OUTF + r) * HH);
        float s = 0.f;
#pragma unroll
        for (int j = 0; j < HH / 128; j++) {
            float4 a = __ldcs(Wr + j * 32 + lane);
            float4 v = xs[j * 32 + lane];
            s += a.x * v.x + a.y * v.y + a.z * v.z + a.w * v.w;
        }
#pragma unroll
        for (int off = 16; off; off >>= 1)
            s += __shfl_xor_sync(0xFFFFFFFFu, s, off);
        if (lane == 0) logits[r] = s + bo[r];
    }
    __syncthreads();

    if (warp == 0) {
        float v[4];
#pragma unroll
        for (int i = 0; i < 4; i++) v[i] = logits[i * 32 + lane];
        float m = fmaxf(fmaxf(v[0], v[1]), fmaxf(v[2], v[3]));
#pragma unroll
        for (int off = 16; off; off >>= 1)
            m = fmaxf(m, __shfl_xor_sync(0xFFFFFFFFu, m, off));
        float s = 0.f;
#pragma unroll
        for (int i = 0; i < 4; i++) s += __expf(v[i] - m);
#pragma unroll
        for (int off = 16; off; off >>= 1)
            s += __shfl_xor_sync(0xFFFFFFFFu, s, off);
        float lse = m + logf(s);
#pragma unroll
        for (int i = 0; i < 4; i++)
            out[b * OUTF + i * 32 + lane] = v[i] - lse;
    }
}

extern "C" void kernel_launch(void* const* d_in, const int* in_sizes, int n_in,
                              void* d_out, int out_size) {
    const float* x      = (const float*)d_in[0];
    const float* hidden = (const float*)d_in[1];
    const float* W0 = (const float*)d_in[2];
    const float* b0 = (const float*)d_in[3];
    const float* W1 = (const float*)d_in[4];
    const float* b1 = (const float*)d_in[5];
    const float* W2 = (const float*)d_in[6];
    const float* b2 = (const float*)d_in[7];
    const float* Wh = (const float*)d_in[8];
    const float* bh = (const float*)d_in[9];
    const float* Wo = (const float*)d_in[10];
    const float* bo = (const float*)d_in[11];

    float* out = (float*)d_out;                 // [B*OUT] log_softmax, then [B*H] new_hidden
    float* new_hidden = out + BB * OUTF;

    float *c0, *c1, *c2;
    cudaGetSymbolAddress((void**)&c0, g_c0);
    cudaGetSymbolAddress((void**)&c1, g_c1);
    cudaGetSymbolAddress((void**)&c2, g_c2);

    // Streams: s1 = chain B main; sb[0], sb[1] = Wo/softmax branches per chain.
    static cudaStream_t s1 = nullptr, sb0 = nullptr, sb1 = nullptr;
    static cudaEvent_t evFork = nullptr, evJoin = nullptr;
    static cudaEvent_t evC2[2] = {}, evWo[2] = {};
    if (!s1) {
        cudaStreamCreateWithFlags(&s1,  cudaStreamNonBlocking);
        cudaStreamCreateWithFlags(&sb0, cudaStreamNonBlocking);
        cudaStreamCreateWithFlags(&sb1, cudaStreamNonBlocking);
        cudaEventCreateWithFlags(&evFork, cudaEventDisableTiming);
        cudaEventCreateWithFlags(&evJoin, cudaEventDisableTiming);
        for (int i = 0; i < 2; i++) {
            cudaEventCreateWithFlags(&evC2[i], cudaEventDisableTiming);
            cudaEventCreateWithFlags(&evWo[i], cudaEventDisableTiming);
        }
    }

    const int BLKS_L = (HB * HH) / RPB;   // 2048 per half-layer
    const int ROFF   = HB * HH;           // row offset of chain B (H layers)

    // Fork chain B off the capture stream.
    cudaEventRecord(evFork, 0);
    cudaStreamWaitEvent(s1, evFork, 0);

    // ---- Chain A (batches 0..15) on default stream; Wo branch on sb0 ----
    matvec_kernel<KCAT, true ><<<BLKS_L, TPB, 0, 0>>>(W0, b0, x,  hidden,  c0, HH, 0);
    matvec_kernel<HH,   false><<<BLKS_L, TPB, 0, 0>>>(W1, b1, c0, nullptr, c1, HH, 0);
    matvec_kernel<HH,   false><<<BLKS_L, TPB, 0, 0>>>(W2, b2, c1, nullptr, c2, HH, 0);
    cudaEventRecord(evC2[0], 0);
    cudaStreamWaitEvent(sb0, evC2[0], 0);
    matvec_kernel<HH,   false><<<BLKS_L, TPB, 0, 0>>>(Wh, bh, c2, nullptr, new_hidden, HH, 0);
    wo_softmax_kernel<<<HB, TPB, 0, sb0>>>(Wo, bo, out, 0);
    cudaEventRecord(evWo[0], sb0);
    cudaStreamWaitEvent(0, evWo[0], 0);

    // ---- Chain B (batches 16..31) on s1; Wo branch on sb1 ----
    matvec_kernel<KCAT, true ><<<BLKS_L, TPB, 0, s1>>>(W0, b0, x,  hidden,  c0, HH, ROFF);
    matvec_kernel<HH,   false><<<BLKS_L, TPB, 0, s1>>>(W1, b1, c0, nullptr, c1, HH, ROFF);
    matvec_kernel<HH,   false><<<BLKS_L, TPB, 0, s1>>>(W2, b2, c1, nullptr, c2, HH, ROFF);
    cudaEventRecord(evC2[1], s1);
    cudaStreamWaitEvent(sb1, evC2[1], 0);
    matvec_kernel<HH,   false><<<BLKS_L, TPB, 0, s1>>>(Wh, bh, c2, nullptr, new_hidden, HH, ROFF);
    wo_softmax_kernel<<<HB, TPB, 0, sb1>>>(Wo, bo, out, HB);
    cudaEventRecord(evWo[1], sb1);
    cudaStreamWaitEvent(s1, evWo[1], 0);

    // Join chain B back to the capture stream.
    cudaEventRecord(evJoin, s1);
    cudaStreamWaitEvent(0, evJoin, 0);

    (void)in_sizes; (void)n_in; (void)out_size;
}

// round 10
// speedup vs baseline: 1.0028x; 1.0028x over previous
#include <cuda_runtime.h>
#include <cuda_bf16.h>
#include <math.h>

// Problem constants
#define BB   32
#define INF  128
#define HH   1024
#define OUTF 128
#define KCAT (INF + HH)   // 1152
#define TPB  256
#define RPB  8            // rows (warps) per block
#define HB   16           // batches per chain (BB/2)

// Scratch (allocation-free rule: __device__ globals)
__device__ float g_c0[BB * HH];
__device__ float g_c1[BB * HH];
__device__ float g_c2[BB * HH];

// ---------------------------------------------------------------------------
// R2/R7-proven matvec tile kernel: 8 warps/block = 8 consecutive rows of ONE
// batch; activation staged in smem once; W front-batched with __ldcs; tanh.
// ---------------------------------------------------------------------------
template <int K, bool LAYER0>
__global__ __launch_bounds__(TPB) void matvec_kernel(
    const float* __restrict__ W, const float* __restrict__ bias,
    const float* __restrict__ in0,   // LAYER0: x ; else: activations [B,K]
    const float* __restrict__ in1,   // LAYER0: hidden ; else unused
    float* __restrict__ out, int Hout, int row_off)
{
    __shared__ float4 xs[K / 4];

    const int rowbase = row_off + blockIdx.x * RPB;
    const int b = rowbase / Hout;

    if (LAYER0) {
        const float4* xv = reinterpret_cast<const float4*>(in0 + (size_t)b * INF);
        const float4* hv = reinterpret_cast<const float4*>(in1 + (size_t)b * HH);
#pragma unroll
        for (int i = threadIdx.x; i < K / 4; i += TPB)
            xs[i] = (i < INF / 4) ? xv[i] : hv[i - INF / 4];
    } else {
        const float4* src = reinterpret_cast<const float4*>(in0 + (size_t)b * K);
#pragma unroll
        for (int i = threadIdx.x; i < K / 4; i += TPB)
            xs[i] = src[i];
    }
    __syncthreads();

    const int warp = threadIdx.x >> 5;
    const int lane = threadIdx.x & 31;
    const int row  = rowbase + warp;
    const int o    = row - b * Hout;

    const float4* __restrict__ Wr = reinterpret_cast<const float4*>(W + (size_t)row * K);
    constexpr int NIT = K / 128;

    float4 w[NIT];
#pragma unroll
    for (int j = 0; j < NIT; j++)
        w[j] = __ldcs(Wr + j * 32 + lane);

    float sum = 0.f;
#pragma unroll
    for (int j = 0; j < NIT; j++) {
        float4 v = xs[j * 32 + lane];
        sum += w[j].x * v.x + w[j].y * v.y + w[j].z * v.z + w[j].w * v.w;
    }
#pragma unroll
    for (int off = 16; off; off >>= 1)
        sum += __shfl_xor_sync(0xFFFFFFFFu, sum, off);

    if (lane == 0)
        out[row] = tanhf(sum + bias[o]);
}

// ---------------------------------------------------------------------------
// Fused heads (half-batch): blocks [0, NBH) -> Wh tiles (tanh -> new_hidden);
// blocks [NBH, NBH+HB) -> one batch each: full Wo matvec + log_softmax -> out.
// ---------------------------------------------------------------------------
__global__ __launch_bounds__(TPB) void heads_kernel(
    const float* __restrict__ Wh, const float* __restrict__ bh,
    const float* __restrict__ Wo, const float* __restrict__ bo,
    float* __restrict__ new_hidden_out, float* __restrict__ out, int boff)
{
    __shared__ float4 xs[HH / 4];
    __shared__ float logits[OUTF];

    const int NBH = (HB * HH) / RPB;   // 2048 Wh blocks per chain
    const int warp = threadIdx.x >> 5;
    const int lane = threadIdx.x & 31;

    if (blockIdx.x < NBH) {
        // ---- Wh tile path (identical to R7) ----
        const int rowbase = boff * HH + blockIdx.x * RPB;
        const int b = rowbase / HH;

        const float4* src = reinterpret_cast<const float4*>(g_c2 + (size_t)b * HH);
#pragma unroll
        for (int i = threadIdx.x; i < HH / 4; i += TPB)
            xs[i] = src[i];
        __syncthreads();

        const int row = rowbase + warp;
        const int o   = row - b * HH;
        const float4* __restrict__ Wr = reinterpret_cast<const float4*>(Wh + (size_t)row * HH);

        float4 w[HH / 128];
#pragma unroll
        for (int j = 0; j < HH / 128; j++)
            w[j] = __ldcs(Wr + j * 32 + lane);

        float sum = 0.f;
#pragma unroll
        for (int j = 0; j < HH / 128; j++) {
            float4 v = xs[j * 32 + lane];
            sum += w[j].x * v.x + w[j].y * v.y + w[j].z * v.z + w[j].w * v.w;
        }
#pragma unroll
        for (int off = 16; off; off >>= 1)
            sum += __shfl_xor_sync(0xFFFFFFFFu, sum, off);

        if (lane == 0)
            new_hidden_out[row] = tanhf(sum + bh[o]);
    } else {
        // ---- Fused Wo + log_softmax: one block per batch ----
        const int b = boff + (blockIdx.x - NBH);

        const float4* src = reinterpret_cast<const float4*>(g_c2 + (size_t)b * HH);
#pragma unroll
        for (int i = threadIdx.x; i < HH / 4; i += TPB)
            xs[i] = src[i];
        __syncthreads();

        for (int r = warp; r < OUTF; r += 8) {
            const float4* __restrict__ Wr =
                reinterpret_cast<const float4*>(Wo + ((size_t)b * OUTF + r) * HH);
            float s = 0.f;
#pragma unroll
            for (int j = 0; j < HH / 128; j++) {
                float4 a = __ldcs(Wr + j * 32 + lane);
                float4 v = xs[j * 32 + lane];
                s += a.x * v.x + a.y * v.y + a.z * v.z + a.w * v.w;
            }
#pragma unroll
            for (int off = 16; off; off >>= 1)
                s += __shfl_xor_sync(0xFFFFFFFFu, s, off);
            if (lane == 0) logits[r] = s + bo[r];
        }
        __syncthreads();

        if (warp == 0) {
            float v[4];
#pragma unroll
            for (int i = 0; i < 4; i++) v[i] = logits[i * 32 + lane];
            float m = fmaxf(fmaxf(v[0], v[1]), fmaxf(v[2], v[3]));
#pragma unroll
            for (int off = 16; off; off >>= 1)
                m = fmaxf(m, __shfl_xor_sync(0xFFFFFFFFu, m, off));
            float s = 0.f;
#pragma unroll
            for (int i = 0; i < 4; i++) s += __expf(v[i] - m);
#pragma unroll
            for (int off = 16; off; off >>= 1)
                s += __shfl_xor_sync(0xFFFFFFFFu, s, off);
            float lse = m + logf(s);
#pragma unroll
            for (int i = 0; i < 4; i++)
                out[b * OUTF + i * 32 + lane] = v[i] - lse;
        }
    }
}

extern "C" void kernel_launch(void* const* d_in, const int* in_sizes, int n_in,
                              void* d_out, int out_size) {
    const float* x      = (const float*)d_in[0];
    const float* hidden = (const float*)d_in[1];
    const float* W0 = (const float*)d_in[2];
    const float* b0 = (const float*)d_in[3];
    const float* W1 = (const float*)d_in[4];
    const float* b1 = (const float*)d_in[5];
    const float* W2 = (const float*)d_in[6];
    const float* b2 = (const float*)d_in[7];
    const float* Wh = (const float*)d_in[8];
    const float* bh = (const float*)d_in[9];
    const float* Wo = (const float*)d_in[10];
    const float* bo = (const float*)d_in[11];

    float* out = (float*)d_out;                 // [B*OUT] log_softmax, then [B*H] new_hidden
    float* new_hidden = out + BB * OUTF;

    float *c0, *c1, *c2;
    cudaGetSymbolAddress((void**)&c0, g_c0);
    cudaGetSymbolAddress((void**)&c1, g_c1);
    cudaGetSymbolAddress((void**)&c2, g_c2);

    // One side stream + fork/join events (identical topology to R7).
    static cudaStream_t s1 = nullptr;
    static cudaEvent_t evFork = nullptr, evJoin = nullptr;
    if (!s1) {
        cudaStreamCreateWithFlags(&s1, cudaStreamNonBlocking);
        cudaEventCreateWithFlags(&evFork, cudaEventDisableTiming);
        cudaEventCreateWithFlags(&evJoin, cudaEventDisableTiming);
    }

    const int BLKS_L = (HB * HH) / RPB;          // 2048 per half-layer
    const int BLKS_HEADS = BLKS_L + HB;          // 2048 Wh tiles + 16 Wo/softmax blocks
    const int ROFF = HB * HH;                    // 16384 row offset (chain B, H layers)

    // Fork: chain B (batches 16..31) on s1.
    cudaEventRecord(evFork, 0);
    cudaStreamWaitEvent(s1, evFork, 0);

    // Chain A: batches 0..15 on default stream
    matvec_kernel<KCAT, true ><<<BLKS_L, TPB, 0, 0>>>(W0, b0, x,  hidden,  c0, HH, 0);
    matvec_kernel<HH,   false><<<BLKS_L, TPB, 0, 0>>>(W1, b1, c0, nullptr, c1, HH, 0);
    matvec_kernel<HH,   false><<<BLKS_L, TPB, 0, 0>>>(W2, b2, c1, nullptr, c2, HH, 0);
    heads_kernel<<<BLKS_HEADS, TPB, 0, 0>>>(Wh, bh, Wo, bo, new_hidden, out, 0);

    // Chain B: batches 16..31 on s1
    matvec_kernel<KCAT, true ><<<BLKS_L, TPB, 0, s1>>>(W0, b0, x,  hidden,  c0, HH, ROFF);
    matvec_kernel<HH,   false><<<BLKS_L, TPB, 0, s1>>>(W1, b1, c0, nullptr, c1, HH, ROFF);
    matvec_kernel<HH,   false><<<BLKS_L, TPB, 0, s1>>>(W2, b2, c1, nullptr, c2, HH, ROFF);
    heads_kernel<<<BLKS_HEADS, TPB, 0, s1>>>(Wh, bh, Wo, bo, new_hidden, out, HB);

    // Join back to the capture stream.
    cudaEventRecord(evJoin, s1);
    cudaStreamWaitEvent(0, evJoin, 0);

    (void)in_sizes; (void)n_in; (void)out_size;
}

// round 11
// speedup vs baseline: 1.2415x; 1.2381x over previous
#include <cuda_runtime.h>
#include <cuda_bf16.h>
#include <math.h>

// Problem constants
#define BB   32
#define INF  128
#define HH   1024
#define OUTF 128
#define KCAT (INF + HH)   // 1152
#define TPB  256
#define RPB  8            // rows (warps) per block
#define SPLIT 18          // chain A batches [0,18), chain B [18,32) — staggers boundaries

// Scratch (allocation-free rule: __device__ globals)
__device__ float g_c0[BB * HH];
__device__ float g_c1[BB * HH];
__device__ float g_c2[BB * HH];
__device__ float g_logits[BB * OUTF];

// ---------------------------------------------------------------------------
// R2/R7-proven matvec tile kernel: 8 warps/block = 8 consecutive rows of ONE
// batch; activation staged in smem once; W front-batched with __ldcs; tanh.
// ---------------------------------------------------------------------------
template <int K, bool LAYER0>
__global__ __launch_bounds__(TPB) void matvec_kernel(
    const float* __restrict__ W, const float* __restrict__ bias,
    const float* __restrict__ in0,   // LAYER0: x ; else: activations [B,K]
    const float* __restrict__ in1,   // LAYER0: hidden ; else unused
    float* __restrict__ out, int Hout, int row_off)
{
    __shared__ float4 xs[K / 4];

    const int rowbase = row_off + blockIdx.x * RPB;
    const int b = rowbase / Hout;

    if (LAYER0) {
        const float4* xv = reinterpret_cast<const float4*>(in0 + (size_t)b * INF);
        const float4* hv = reinterpret_cast<const float4*>(in1 + (size_t)b * HH);
#pragma unroll
        for (int i = threadIdx.x; i < K / 4; i += TPB)
            xs[i] = (i < INF / 4) ? xv[i] : hv[i - INF / 4];
    } else {
        const float4* src = reinterpret_cast<const float4*>(in0 + (size_t)b * K);
#pragma unroll
        for (int i = threadIdx.x; i < K / 4; i += TPB)
            xs[i] = src[i];
    }
    __syncthreads();

    const int warp = threadIdx.x >> 5;
    const int lane = threadIdx.x & 31;
    const int row  = rowbase + warp;
    const int o    = row - b * Hout;

    const float4* __restrict__ Wr = reinterpret_cast<const float4*>(W + (size_t)row * K);
    constexpr int NIT = K / 128;

    float4 w[NIT];
#pragma unroll
    for (int j = 0; j < NIT; j++)
        w[j] = __ldcs(Wr + j * 32 + lane);

    float sum = 0.f;
#pragma unroll
    for (int j = 0; j < NIT; j++) {
        float4 v = xs[j * 32 + lane];
        sum += w[j].x * v.x + w[j].y * v.y + w[j].z * v.z + w[j].w * v.w;
    }
#pragma unroll
    for (int off = 16; off; off >>= 1)
        sum += __shfl_xor_sync(0xFFFFFFFFu, sum, off);

    if (lane == 0)
        out[row] = tanhf(sum + bias[o]);
}

// Fused heads (R7 tile form, runtime batch count): blocks [0,NBH) -> Wh tiles,
// blocks [NBH, NBH+nb*OUTF/RPB) -> Wo tiles (logits, no tanh).
__global__ __launch_bounds__(TPB) void heads_kernel(
    const float* __restrict__ Wh, const float* __restrict__ bh,
    const float* __restrict__ Wo, const float* __restrict__ bo,
    float* __restrict__ new_hidden_out, int boff, int nbatch)
{
    __shared__ float4 xs[HH / 4];

    const int NBH = (nbatch * HH) / RPB;
    const bool is_h = ((int)blockIdx.x < NBH);
    int rowbase, b, Hout;
    const float* Wbase; const float* bias;
    if (is_h) { rowbase = boff * HH   + blockIdx.x * RPB;         Hout = HH;   Wbase = Wh; bias = bh; }
    else      { rowbase = boff * OUTF + (blockIdx.x - NBH) * RPB; Hout = OUTF; Wbase = Wo; bias = bo; }
    b = rowbase / Hout;

    {
        const float4* src = reinterpret_cast<const float4*>(g_c2 + (size_t)b * HH);
#pragma unroll
        for (int i = threadIdx.x; i < HH / 4; i += TPB)
            xs[i] = src[i];
    }
    __syncthreads();

    const int warp = threadIdx.x >> 5;
    const int lane = threadIdx.x & 31;
    const int row  = rowbase + warp;
    const int o    = row - b * Hout;

    const float4* __restrict__ Wr = reinterpret_cast<const float4*>(Wbase + (size_t)row * HH);
    constexpr int NIT = HH / 128;

    float4 w[NIT];
#pragma unroll
    for (int j = 0; j < NIT; j++)
        w[j] = __ldcs(Wr + j * 32 + lane);

    float sum = 0.f;
#pragma unroll
    for (int j = 0; j < NIT; j++) {
        float4 v = xs[j * 32 + lane];
        sum += w[j].x * v.x + w[j].y * v.y + w[j].z * v.z + w[j].w * v.w;
    }
#pragma unroll
    for (int off = 16; off; off >>= 1)
        sum += __shfl_xor_sync(0xFFFFFFFFu, sum, off);

    if (lane == 0) {
        if (is_h) new_hidden_out[row] = tanhf(sum + bias[o]);
        else      g_logits[row] = sum + bias[o];
    }
}

// log_softmax for batches [boff, boff+nbatch); one warp per batch.
__global__ void log_softmax_kernel(float* __restrict__ out, int boff) {
    const int warp = threadIdx.x >> 5;
    const int lane = threadIdx.x & 31;
    const int bq = boff + warp;
    const float* l = g_logits + bq * OUTF;

    float v[4];
#pragma unroll
    for (int i = 0; i < 4; i++) v[i] = l[i * 32 + lane];

    float m = fmaxf(fmaxf(v[0], v[1]), fmaxf(v[2], v[3]));
#pragma unroll
    for (int off = 16; off; off >>= 1)
        m = fmaxf(m, __shfl_xor_sync(0xFFFFFFFFu, m, off));

    float s = 0.f;
#pragma unroll
    for (int i = 0; i < 4; i++) s += __expf(v[i] - m);
#pragma unroll
    for (int off = 16; off; off >>= 1)
        s += __shfl_xor_sync(0xFFFFFFFFu, s, off);

    float lse = m + logf(s);
#pragma unroll
    for (int i = 0; i < 4; i++)
        out[bq * OUTF + i * 32 + lane] = v[i] - lse;
}

extern "C" void kernel_launch(void* const* d_in, const int* in_sizes, int n_in,
                              void* d_out, int out_size) {
    const float* x      = (const float*)d_in[0];
    const float* hidden = (const float*)d_in[1];
    const float* W0 = (const float*)d_in[2];
    const float* b0 = (const float*)d_in[3];
    const float* W1 = (const float*)d_in[4];
    const float* b1 = (const float*)d_in[5];
    const float* W2 = (const float*)d_in[6];
    const float* b2 = (const float*)d_in[7];
    const float* Wh = (const float*)d_in[8];
    const float* bh = (const float*)d_in[9];
    const float* Wo = (const float*)d_in[10];
    const float* bo = (const float*)d_in[11];

    float* out = (float*)d_out;                 // [B*OUT] log_softmax, then [B*H] new_hidden
    float* new_hidden = out + BB * OUTF;

    float *c0, *c1, *c2;
    cudaGetSymbolAddress((void**)&c0, g_c0);
    cudaGetSymbolAddress((void**)&c1, g_c1);
    cudaGetSymbolAddress((void**)&c2, g_c2);

    // One side stream + fork/join events (identical topology to R7).
    static cudaStream_t s1 = nullptr;
    static cudaEvent_t evFork = nullptr, evJoin = nullptr;
    if (!s1) {
        cudaStreamCreateWithFlags(&s1, cudaStreamNonBlocking);
        cudaEventCreateWithFlags(&evFork, cudaEventDisableTiming);
        cudaEventCreateWithFlags(&evJoin, cudaEventDisableTiming);
    }

    const int NA = SPLIT;            // 18 batches, chain A
    const int NB = BB - SPLIT;       // 14 batches, chain B
    const int BLKS_LA = (NA * HH) / RPB;                 // 2304
    const int BLKS_LB = (NB * HH) / RPB;                 // 1792
    const int BLKS_HA = BLKS_LA + (NA * OUTF) / RPB;     // 2592
    const int BLKS_HB = BLKS_LB + (NB * OUTF) / RPB;     // 2016
    const int ROFF = NA * HH;                            // chain B row offset (H layers)

    // Fork: chain B on s1.
    cudaEventRecord(evFork, 0);
    cudaStreamWaitEvent(s1, evFork, 0);

    // Chain A: batches [0, 18) on default stream
    matvec_kernel<KCAT, true ><<<BLKS_LA, TPB, 0, 0>>>(W0, b0, x,  hidden,  c0, HH, 0);
    matvec_kernel<HH,   false><<<BLKS_LA, TPB, 0, 0>>>(W1, b1, c0, nullptr, c1, HH, 0);
    matvec_kernel<HH,   false><<<BLKS_LA, TPB, 0, 0>>>(W2, b2, c1, nullptr, c2, HH, 0);
    heads_kernel<<<BLKS_HA, TPB, 0, 0>>>(Wh, bh, Wo, bo, new_hidden, 0, NA);
    log_softmax_kernel<<<1, NA * 32, 0, 0>>>(out, 0);

    // Chain B: batches [18, 32) on s1
    matvec_kernel<KCAT, true ><<<BLKS_LB, TPB, 0, s1>>>(W0, b0, x,  hidden,  c0, HH, ROFF);
    matvec_kernel<HH,   false><<<BLKS_LB, TPB, 0, s1>>>(W1, b1, c0, nullptr, c1, HH, ROFF);
    matvec_kernel<HH,   false><<<BLKS_LB, TPB, 0, s1>>>(W2, b2, c1, nullptr, c2, HH, ROFF);
    heads_kernel<<<BLKS_HB, TPB, 0, s1>>>(Wh, bh, Wo, bo, new_hidden, NA, NB);
    log_softmax_kernel<<<1, NB * 32, 0, s1>>>(out, NA);

    // Join back to the capture stream.
    cudaEventRecord(evJoin, s1);
    cudaStreamWaitEvent(0, evJoin, 0);

    (void)in_sizes; (void)n_in; (void)out_size;
}

// round 12
// speedup vs baseline: 1.2586x; 1.0138x over previous
#include <cuda_runtime.h>
#include <cuda_bf16.h>
#include <math.h>

// Problem constants
#define BB   32
#define INF  128
#define HH   1024
#define OUTF 128
#define KCAT (INF + HH)   // 1152
#define TPB  256
#define RPB  8            // rows (warps) per block
#define NCH  3            // chains: 11 / 11 / 10 batches

// Scratch (allocation-free rule: __device__ globals)
__device__ float g_c0[BB * HH];
__device__ float g_c1[BB * HH];
__device__ float g_c2[BB * HH];
__device__ float g_logits[BB * OUTF];

// ---------------------------------------------------------------------------
// R2/R7-proven matvec tile kernel: 8 warps/block = 8 consecutive rows of ONE
// batch; activation staged in smem once; W front-batched with __ldcs; tanh.
// ---------------------------------------------------------------------------
template <int K, bool LAYER0>
__global__ __launch_bounds__(TPB) void matvec_kernel(
    const float* __restrict__ W, const float* __restrict__ bias,
    const float* __restrict__ in0,   // LAYER0: x ; else: activations [B,K]
    const float* __restrict__ in1,   // LAYER0: hidden ; else unused
    float* __restrict__ out, int Hout, int row_off)
{
    __shared__ float4 xs[K / 4];

    const int rowbase = row_off + blockIdx.x * RPB;
    const int b = rowbase / Hout;

    if (LAYER0) {
        const float4* xv = reinterpret_cast<const float4*>(in0 + (size_t)b * INF);
        const float4* hv = reinterpret_cast<const float4*>(in1 + (size_t)b * HH);
#pragma unroll
        for (int i = threadIdx.x; i < K / 4; i += TPB)
            xs[i] = (i < INF / 4) ? xv[i] : hv[i - INF / 4];
    } else {
        const float4* src = reinterpret_cast<const float4*>(in0 + (size_t)b * K);
#pragma unroll
        for (int i = threadIdx.x; i < K / 4; i += TPB)
            xs[i] = src[i];
    }
    __syncthreads();

    const int warp = threadIdx.x >> 5;
    const int lane = threadIdx.x & 31;
    const int row  = rowbase + warp;
    const int o    = row - b * Hout;

    const float4* __restrict__ Wr = reinterpret_cast<const float4*>(W + (size_t)row * K);
    constexpr int NIT = K / 128;

    float4 w[NIT];
#pragma unroll
    for (int j = 0; j < NIT; j++)
        w[j] = __ldcs(Wr + j * 32 + lane);

    float sum = 0.f;
#pragma unroll
    for (int j = 0; j < NIT; j++) {
        float4 v = xs[j * 32 + lane];
        sum += w[j].x * v.x + w[j].y * v.y + w[j].z * v.z + w[j].w * v.w;
    }
#pragma unroll
    for (int off = 16; off; off >>= 1)
        sum += __shfl_xor_sync(0xFFFFFFFFu, sum, off);

    if (lane == 0)
        out[row] = tanhf(sum + bias[o]);
}

// Fused heads (runtime batch count): blocks [0,NBH) -> Wh tiles (tanh),
// blocks [NBH, ...) -> Wo tiles (logits, no tanh).
__global__ __launch_bounds__(TPB) void heads_kernel(
    const float* __restrict__ Wh, const float* __restrict__ bh,
    const float* __restrict__ Wo, const float* __restrict__ bo,
    float* __restrict__ new_hidden_out, int boff, int nbatch)
{
    __shared__ float4 xs[HH / 4];

    const int NBH = (nbatch * HH) / RPB;
    const bool is_h = ((int)blockIdx.x < NBH);
    int rowbase, b, Hout;
    const float* Wbase; const float* bias;
    if (is_h) { rowbase = boff * HH   + blockIdx.x * RPB;         Hout = HH;   Wbase = Wh; bias = bh; }
    else      { rowbase = boff * OUTF + (blockIdx.x - NBH) * RPB; Hout = OUTF; Wbase = Wo; bias = bo; }
    b = rowbase / Hout;

    {
        const float4* src = reinterpret_cast<const float4*>(g_c2 + (size_t)b * HH);
#pragma unroll
        for (int i = threadIdx.x; i < HH / 4; i += TPB)
            xs[i] = src[i];
    }
    __syncthreads();

    const int warp = threadIdx.x >> 5;
    const int lane = threadIdx.x & 31;
    const int row  = rowbase + warp;
    const int o    = row - b * Hout;

    const float4* __restrict__ Wr = reinterpret_cast<const float4*>(Wbase + (size_t)row * HH);
    constexpr int NIT = HH / 128;

    float4 w[NIT];
#pragma unroll
    for (int j = 0; j < NIT; j++)
        w[j] = __ldcs(Wr + j * 32 + lane);

    float sum = 0.f;
#pragma unroll
    for (int j = 0; j < NIT; j++) {
        float4 v = xs[j * 32 + lane];
        sum += w[j].x * v.x + w[j].y * v.y + w[j].z * v.z + w[j].w * v.w;
    }
#pragma unroll
    for (int off = 16; off; off >>= 1)
        sum += __shfl_xor_sync(0xFFFFFFFFu, sum, off);

    if (lane == 0) {
        if (is_h) new_hidden_out[row] = tanhf(sum + bias[o]);
        else      g_logits[row] = sum + bias[o];
    }
}

// log_softmax for batches [boff, boff+nwarps); one warp per batch.
__global__ void log_softmax_kernel(float* __restrict__ out, int boff) {
    const int warp = threadIdx.x >> 5;
    const int lane = threadIdx.x & 31;
    const int bq = boff + warp;
    const float* l = g_logits + bq * OUTF;

    float v[4];
#pragma unroll
    for (int i = 0; i < 4; i++) v[i] = l[i * 32 + lane];

    float m = fmaxf(fmaxf(v[0], v[1]), fmaxf(v[2], v[3]));
#pragma unroll
    for (int off = 16; off; off >>= 1)
        m = fmaxf(m, __shfl_xor_sync(0xFFFFFFFFu, m, off));

    float s = 0.f;
#pragma unroll
    for (int i = 0; i < 4; i++) s += __expf(v[i] - m);
#pragma unroll
    for (int off = 16; off; off >>= 1)
        s += __shfl_xor_sync(0xFFFFFFFFu, s, off);

    float lse = m + logf(s);
#pragma unroll
    for (int i = 0; i < 4; i++)
        out[bq * OUTF + i * 32 + lane] = v[i] - lse;
}

extern "C" void kernel_launch(void* const* d_in, const int* in_sizes, int n_in,
                              void* d_out, int out_size) {
    const float* x      = (const float*)d_in[0];
    const float* hidden = (const float*)d_in[1];
    const float* W0 = (const float*)d_in[2];
    const float* b0 = (const float*)d_in[3];
    const float* W1 = (const float*)d_in[4];
    const float* b1 = (const float*)d_in[5];
    const float* W2 = (const float*)d_in[6];
    const float* b2 = (const float*)d_in[7];
    const float* Wh = (const float*)d_in[8];
    const float* bh = (const float*)d_in[9];
    const float* Wo = (const float*)d_in[10];
    const float* bo = (const float*)d_in[11];

    float* out = (float*)d_out;                 // [B*OUT] log_softmax, then [B*H] new_hidden
    float* new_hidden = out + BB * OUTF;

    float *c0, *c1, *c2;
    cudaGetSymbolAddress((void**)&c0, g_c0);
    cudaGetSymbolAddress((void**)&c1, g_c1);
    cudaGetSymbolAddress((void**)&c2, g_c2);

    // Two side streams + fork/join events (R7-proven pattern, one extra chain).
    static cudaStream_t st[NCH - 1] = {};
    static cudaEvent_t evFork = nullptr, evJoin[NCH - 1] = {};
    if (!st[0]) {
        for (int i = 0; i < NCH - 1; i++) {
            cudaStreamCreateWithFlags(&st[i], cudaStreamNonBlocking);
            cudaEventCreateWithFlags(&evJoin[i], cudaEventDisableTiming);
        }
        cudaEventCreateWithFlags(&evFork, cudaEventDisableTiming);
    }

    // Chain batch partitions: 11 / 11 / 10
    const int nbat[NCH] = {11, 11, 10};
    const int boff[NCH] = {0, 11, 22};

    // Fork side chains off the capture (default) stream.
    cudaEventRecord(evFork, 0);
    for (int i = 0; i < NCH - 1; i++)
        cudaStreamWaitEvent(st[i], evFork, 0);

    for (int ch = 0; ch < NCH; ch++) {
        cudaStream_t s = (ch == 0) ? (cudaStream_t)0 : st[ch - 1];
        const int nb = nbat[ch];
        const int bo_ = boff[ch];
        const int roff = bo_ * HH;
        const int blksL = (nb * HH) / RPB;
        const int blksH = blksL + (nb * OUTF) / RPB;

        matvec_kernel<KCAT, true ><<<blksL, TPB, 0, s>>>(W0, b0, x,  hidden,  c0, HH, roff);
        matvec_kernel<HH,   false><<<blksL, TPB, 0, s>>>(W1, b1, c0, nullptr, c1, HH, roff);
        matvec_kernel<HH,   false><<<blksL, TPB, 0, s>>>(W2, b2, c1, nullptr, c2, HH, roff);
        heads_kernel<<<blksH, TPB, 0, s>>>(Wh, bh, Wo, bo, new_hidden, bo_, nb);
        log_softmax_kernel<<<1, nb * 32, 0, s>>>(out, bo_);
    }

    // Join side chains back to the capture stream.
    for (int i = 0; i < NCH - 1; i++) {
        cudaEventRecord(evJoin[i], st[i]);
        cudaStreamWaitEvent(0, evJoin[i], 0);
    }

    (void)in_sizes; (void)n_in; (void)out_size;
}